// round 15
// baseline (speedup 1.0000x reference)
#include <cuda_runtime.h>
#include <math.h>

#define B_ 2
#define S_ 1024
#define D_ 768
#define H_ 12
#define E_ 8
#define DH_ 64
#define DFF_ 2048
#define NTOK (B_*S_)
#define CAP_ 320
#define NOUT (NTOK*D_)

// ---------------- scratch (device globals; no allocation allowed) -------------
__device__ float g_xln [NTOK*D_];
__device__ float g_q   [NTOK*D_];
__device__ float g_k   [NTOK*D_];
__device__ float g_vsel[NTOK*D_];
__device__ float g_attn[NTOK*D_];
__device__ float g_x1  [NTOK*D_];
__device__ float g_xln2[NTOK*D_];
__device__ float g_rlog[NTOK*(H_*E_)];
__device__ int   g_hcnt[H_*E_];
__device__ int   g_hlist[H_*E_*NTOK];
__device__ float g_m[B_*H_*S_];
__device__ float g_l[B_*H_*S_];
__device__ int   g_tk_idx[NTOK*2];
__device__ float g_tk_prob[NTOK*2];
__device__ int   g_token_slot[NTOK*2];
__device__ int   g_slot_token[E_*CAP_];
__device__ float g_slot_w[E_*CAP_];
__device__ int   g_ecount[E_];
__device__ float g_hbuf[E_*CAP_*DFF_];
__device__ float g_sout[E_*CAP_*D_];

// ---------------- tf32 tensor-core helpers -------------------------------------
__device__ __forceinline__ unsigned to_tf32(float f) {
    unsigned u; asm("cvt.rna.tf32.f32 %0,%1;" : "=r"(u) : "f"(f)); return u;
}
__device__ __forceinline__ void mma_tf32(float c[4], const unsigned a[4], const unsigned b[2]) {
    asm("mma.sync.aligned.m16n8k8.row.col.f32.tf32.tf32.f32 "
        "{%0,%1,%2,%3},{%4,%5,%6,%7},{%8,%9},{%0,%1,%2,%3};"
        : "+f"(c[0]), "+f"(c[1]), "+f"(c[2]), "+f"(c[3])
        : "r"(a[0]), "r"(a[1]), "r"(a[2]), "r"(a[3]), "r"(b[0]), "r"(b[1]));
}
__device__ __forceinline__ void cp16(void* smem, const void* g) {
    unsigned saddr = (unsigned)__cvta_generic_to_shared(smem);
    asm volatile("cp.async.cg.shared.global [%0], [%1], 16;" :: "r"(saddr), "l"(g));
}
#define CP_COMMIT() asm volatile("cp.async.commit_group;" ::: "memory")
#define CP_WAIT0()  asm volatile("cp.async.wait_group 0;" ::: "memory")

// ---------------- LayerNorm (warp per row, float4); optional counter clear -----
__global__ void ln_kernel(const float* __restrict__ x, const float* __restrict__ g,
                          const float* __restrict__ b, float* __restrict__ out,
                          int clear_hard) {
    if (clear_hard && blockIdx.x == 0 && threadIdx.x < H_ * E_) g_hcnt[threadIdx.x] = 0;
    int wid = threadIdx.x >> 5, lane = threadIdx.x & 31;
    int row = blockIdx.x * 8 + wid;
    const float4* xr = (const float4*)(x + (size_t)row * D_);
    float4 v[6];
    float s = 0.f, s2 = 0.f;
#pragma unroll
    for (int i = 0; i < 6; i++) {
        v[i] = xr[lane + i * 32];
        s  += v[i].x + v[i].y + v[i].z + v[i].w;
        s2 += v[i].x * v[i].x + v[i].y * v[i].y + v[i].z * v[i].z + v[i].w * v[i].w;
    }
#pragma unroll
    for (int o = 16; o > 0; o >>= 1) {
        s  += __shfl_xor_sync(0xffffffffu, s,  o);
        s2 += __shfl_xor_sync(0xffffffffu, s2, o);
    }
    float mean = s * (1.f / D_);
    float inv  = rsqrtf(s2 * (1.f / D_) - mean * mean + 1e-5f);
    float4* orow = (float4*)(out + (size_t)row * D_);
    const float4* g4 = (const float4*)g;
    const float4* b4 = (const float4*)b;
#pragma unroll
    for (int i = 0; i < 6; i++) {
        float4 gg = g4[lane + i * 32], bb = b4[lane + i * 32];
        float4 o;
        o.x = (v[i].x - mean) * inv * gg.x + bb.x;
        o.y = (v[i].y - mean) * inv * gg.y + bb.y;
        o.z = (v[i].z - mean) * inv * gg.z + bb.z;
        o.w = (v[i].w - mean) * inv * gg.w + bb.w;
        orow[lane + i * 32] = o;
    }
}

// ---------------- LN2 + FFN gate fused (warp per row, gff staged in smem) ------
__global__ void ln_gate_kernel(const float* __restrict__ x, const float* __restrict__ g,
                               const float* __restrict__ b, const float* __restrict__ gff,
                               float* __restrict__ out) {
    __shared__ float sgff[D_ * E_];   // 24 KB
    int tid = threadIdx.x;
    for (int i = tid; i < (D_ * E_) / 4; i += 256)
        *(float4*)&sgff[i * 4] = *(const float4*)(gff + i * 4);

    int wid = tid >> 5, lane = tid & 31;
    int row = blockIdx.x * 8 + wid;
    const float4* xr = (const float4*)(x + (size_t)row * D_);
    float4 v[6];
    float s = 0.f, s2 = 0.f;
#pragma unroll
    for (int i = 0; i < 6; i++) {
        v[i] = xr[lane + i * 32];
        s  += v[i].x + v[i].y + v[i].z + v[i].w;
        s2 += v[i].x * v[i].x + v[i].y * v[i].y + v[i].z * v[i].z + v[i].w * v[i].w;
    }
#pragma unroll
    for (int o = 16; o > 0; o >>= 1) {
        s  += __shfl_xor_sync(0xffffffffu, s,  o);
        s2 += __shfl_xor_sync(0xffffffffu, s2, o);
    }
    float mean = s * (1.f / D_);
    float inv  = rsqrtf(s2 * (1.f / D_) - mean * mean + 1e-5f);
    float4* orow = (float4*)(out + (size_t)row * D_);
    const float4* g4 = (const float4*)g;
    const float4* b4 = (const float4*)b;
    __syncthreads();
    float acc[8] = {};
#pragma unroll
    for (int i = 0; i < 6; i++) {
        int c = lane + i * 32;
        float4 gg = g4[c], bb = b4[c];
        float4 o;
        o.x = (v[i].x - mean) * inv * gg.x + bb.x;
        o.y = (v[i].y - mean) * inv * gg.y + bb.y;
        o.z = (v[i].z - mean) * inv * gg.z + bb.z;
        o.w = (v[i].w - mean) * inv * gg.w + bb.w;
        orow[c] = o;
        float ov[4] = { o.x, o.y, o.z, o.w };
#pragma unroll
        for (int j = 0; j < 4; j++) {
            float xv = ov[j];
            const float* gr = &sgff[(c * 4 + j) * E_];
            float4 gA = *(const float4*)gr;
            float4 gB = *(const float4*)(gr + 4);
            acc[0] += xv * gA.x; acc[1] += xv * gA.y; acc[2] += xv * gA.z; acc[3] += xv * gA.w;
            acc[4] += xv * gB.x; acc[5] += xv * gB.y; acc[6] += xv * gB.z; acc[7] += xv * gB.w;
        }
    }
#pragma unroll
    for (int off = 16; off > 0; off >>= 1)
#pragma unroll
        for (int i = 0; i < 8; i++)
            acc[i] += __shfl_down_sync(0xffffffffu, acc[i], off);
    if (lane == 0) {
        int i0 = 0; float v0 = acc[0];
#pragma unroll
        for (int e = 1; e < E_; e++) if (acc[e] > v0) { v0 = acc[e]; i0 = e; }
        int i1 = -1; float v1 = -3.4e38f;
#pragma unroll
        for (int e = 0; e < E_; e++) { if (e == i0) continue; if (acc[e] > v1) { v1 = acc[e]; i1 = e; } }
        float e1 = expf(v1 - v0);
        float z = 1.f + e1;
        g_tk_idx[row * 2] = i0; g_tk_idx[row * 2 + 1] = i1;
        g_tk_prob[row * 2] = 1.f / z; g_tk_prob[row * 2 + 1] = e1 / z;
    }
}

// ---------------- tf32 GEMM, 128x64x16 tiles, cp.async double buffered ---------
#define ASTRIDE 20
#define BSTRIDE 72
template<int MODE>
__global__ __launch_bounds__(256)
void gemm_tf32(const float* __restrict__ P0, const float* __restrict__ P1,
               const float* __restrict__ P2) {
    __shared__ __align__(16) unsigned As[2][128 * ASTRIDE];
    __shared__ __align__(16) unsigned Bs[2][16 * BSTRIDE];

    const int tid = threadIdx.x, wid = tid >> 5, lane = tid & 31;
    const int e  = blockIdx.z;
    const int m0 = blockIdx.y * 128;

    int N, K, count, n0;
    const float* Bm;
    float* C;
    const float* Abase;
    if (MODE == 0) {
        K = D_; count = NTOK; Abase = g_xln;
        int bx = blockIdx.x;
        if (bx < 12)      { Bm = P0; C = g_q;    N = D_; n0 = bx * 64; }
        else if (bx < 24) { Bm = P1; C = g_k;    N = D_; n0 = (bx - 12) * 64; }
        else              { Bm = P2; C = g_rlog; N = 96; n0 = (bx - 24) * 64; }
    } else if (MODE == 1) {
        N = DFF_; K = D_; count = g_ecount[e]; n0 = blockIdx.x * 64;
        if (count <= 0 || m0 >= count) return;
        Bm = P0 + (size_t)e * D_ * DFF_;
        C  = g_hbuf + (size_t)e * CAP_ * DFF_;
        Abase = g_xln2;
    } else {
        N = D_; K = DFF_; count = g_ecount[e]; n0 = blockIdx.x * 64;
        if (count <= 0 || m0 >= count) return;
        Bm = P0 + (size_t)e * DFF_ * D_;
        C  = g_sout + (size_t)e * CAP_ * D_;
        Abase = g_hbuf + (size_t)e * CAP_ * DFF_;
    }

    const int sm_r = tid >> 1;
    const int sm_k = (tid & 1) * 8;
    const int brow = tid >> 4;
    const int bcol = (tid & 15) * 4;

    const float* Aptr;
    {
        int r = m0 + sm_r;
        if (r >= count) r = count - 1;
        if (MODE == 1)
            Aptr = Abase + (size_t)g_slot_token[e * CAP_ + r] * D_ + sm_k;
        else
            Aptr = Abase + (size_t)r * K + sm_k;
    }
    int bc_eff = bcol;
    if (n0 + bcol + 4 > N) bc_eff = N - 4 - n0;
    const float* Bptr = Bm + (size_t)brow * N + n0 + bc_eff;

    const int wm0 = (wid & 3) * 32;
    const int wn0 = (wid >> 2) * 32;
    const int gr = lane >> 2, gc = lane & 3;

    float acc[2][4][4];
#pragma unroll
    for (int i = 0; i < 2; i++)
#pragma unroll
        for (int j = 0; j < 4; j++)
#pragma unroll
            for (int q = 0; q < 4; q++) acc[i][j][q] = 0.f;

    const int nk = K / 16;

    cp16(&As[0][sm_r * ASTRIDE + sm_k],     Aptr);
    cp16(&As[0][sm_r * ASTRIDE + sm_k + 4], Aptr + 4);
    cp16(&Bs[0][brow * BSTRIDE + bcol],     Bptr);
    CP_COMMIT();

    for (int kb = 0; kb < nk; kb++) {
        const int buf = kb & 1;
        CP_WAIT0();
        __syncthreads();
        if (kb + 1 < nk) {
            cp16(&As[buf ^ 1][sm_r * ASTRIDE + sm_k],     Aptr + (kb + 1) * 16);
            cp16(&As[buf ^ 1][sm_r * ASTRIDE + sm_k + 4], Aptr + (kb + 1) * 16 + 4);
            cp16(&Bs[buf ^ 1][brow * BSTRIDE + bcol],     Bptr + (size_t)(kb + 1) * 16 * N);
            CP_COMMIT();
        }
        const unsigned* Ab = As[buf];
        const unsigned* Bb = Bs[buf];
#pragma unroll
        for (int kk = 0; kk < 16; kk += 8) {
            unsigned a[2][4];
#pragma unroll
            for (int mf = 0; mf < 2; mf++) {
                int mb = wm0 + mf * 16;
                a[mf][0] = Ab[(mb + gr)     * ASTRIDE + kk + gc];
                a[mf][1] = Ab[(mb + gr + 8) * ASTRIDE + kk + gc];
                a[mf][2] = Ab[(mb + gr)     * ASTRIDE + kk + gc + 4];
                a[mf][3] = Ab[(mb + gr + 8) * ASTRIDE + kk + gc + 4];
            }
#pragma unroll
            for (int nf = 0; nf < 4; nf++) {
                int nb = wn0 + nf * 8 + gr;
                unsigned b[2];
                b[0] = Bb[(kk + gc)     * BSTRIDE + nb];
                b[1] = Bb[(kk + gc + 4) * BSTRIDE + nb];
                mma_tf32(acc[0][nf], a[0], b);
                mma_tf32(acc[1][nf], a[1], b);
            }
        }
    }

#pragma unroll
    for (int mf = 0; mf < 2; mf++) {
        int rbase = m0 + wm0 + mf * 16 + gr;
#pragma unroll
        for (int half = 0; half < 2; half++) {
            int r = rbase + half * 8;
            if (MODE != 0 && r >= count) continue;
            float w = 1.f;
            if (MODE == 2) w = g_slot_w[e * CAP_ + r];
#pragma unroll
            for (int nf = 0; nf < 4; nf++) {
                int cc = n0 + wn0 + nf * 8 + gc * 2;
                if (MODE == 0 && cc + 2 > N) continue;
                float v0 = acc[mf][nf][half * 2 + 0];
                float v1 = acc[mf][nf][half * 2 + 1];
                if (MODE == 1) { v0 = fmaxf(v0, 0.f); v1 = fmaxf(v1, 0.f); }
                else if (MODE == 2) { v0 *= w; v1 *= w; }
                *(float2*)(C + (size_t)r * N + cc) = make_float2(v0, v1);
            }
        }
    }
}

// ---------------- router argmax + per-(h,e) token list build -------------------
__global__ void router_argmax() {
    int idx = blockIdx.x * 256 + threadIdx.x;
    if (idx >= NTOK * H_) return;
    int row = idx / H_, h = idx - row * H_;
    const float* lg = g_rlog + (size_t)row * 96 + h * 8;
    float best = lg[0]; int bi = 0;
#pragma unroll
    for (int e = 1; e < E_; e++) { float v = lg[e]; if (v > best) { best = v; bi = e; } }
    int he = h * E_ + bi;
    int pos = atomicAdd(&g_hcnt[he], 1);
    g_hlist[(size_t)he * NTOK + pos] = row;
}

// ---------------- sel_gemm device body (vsel / osel) ---------------------------
template<int MODE>
__device__ __forceinline__ void sel_body(const float* __restrict__ W,
                                         const float* __restrict__ xres,
                                         int he, int tile, unsigned* smem) {
    unsigned* Xs = smem;
    unsigned* Ws = smem + 64 * 68;
    int* ts = (int*)(smem + 2 * 64 * 68);
    const int count = g_hcnt[he];
    const int h = he >> 3;
    const int tid = threadIdx.x, wid = tid >> 5, lane = tid & 31;
    const int gr = lane >> 2, gc = lane & 3;

    if (tid < 64) {
        int idx = tile * 64 + tid;
        if (idx >= count) idx = count - 1;
        ts[tid] = g_hlist[(size_t)he * NTOK + idx];
    }
    __syncthreads();

    {
        int r = tid >> 2, cg = (tid & 3) * 16;
        const float* wsrc = W + (size_t)he * DH_ * DH_ + r * DH_ + cg;
        const float* xsrc = (MODE == 0 ? g_xln : g_attn) + (size_t)ts[r] * D_ + h * DH_ + cg;
#pragma unroll
        for (int i = 0; i < 4; i++) {
            float4 wv = *(const float4*)(wsrc + i * 4);
            Ws[r * 68 + cg + i * 4 + 0] = __float_as_uint(wv.x);
            Ws[r * 68 + cg + i * 4 + 1] = __float_as_uint(wv.y);
            Ws[r * 68 + cg + i * 4 + 2] = __float_as_uint(wv.z);
            Ws[r * 68 + cg + i * 4 + 3] = __float_as_uint(wv.w);
            float4 xv = *(const float4*)(xsrc + i * 4);
            Xs[r * 68 + cg + i * 4 + 0] = __float_as_uint(xv.x);
            Xs[r * 68 + cg + i * 4 + 1] = __float_as_uint(xv.y);
            Xs[r * 68 + cg + i * 4 + 2] = __float_as_uint(xv.z);
            Xs[r * 68 + cg + i * 4 + 3] = __float_as_uint(xv.w);
        }
    }
    __syncthreads();

    const int wm0 = (wid & 1) * 32, wn0 = (wid >> 1) * 16;
    float c[2][2][4];
#pragma unroll
    for (int mf = 0; mf < 2; mf++)
#pragma unroll
        for (int nf = 0; nf < 2; nf++)
#pragma unroll
            for (int q = 0; q < 4; q++) c[mf][nf][q] = 0.f;
#pragma unroll
    for (int kk = 0; kk < 64; kk += 8) {
        unsigned a[2][4], bf[2][2];
#pragma unroll
        for (int mf = 0; mf < 2; mf++) {
            int mb = wm0 + mf * 16;
            a[mf][0] = Xs[(mb + gr)     * 68 + kk + gc];
            a[mf][1] = Xs[(mb + gr + 8) * 68 + kk + gc];
            a[mf][2] = Xs[(mb + gr)     * 68 + kk + gc + 4];
            a[mf][3] = Xs[(mb + gr + 8) * 68 + kk + gc + 4];
        }
#pragma unroll
        for (int nf = 0; nf < 2; nf++) {
            int nb = wn0 + nf * 8 + gr;
            bf[nf][0] = Ws[(kk + gc)     * 68 + nb];
            bf[nf][1] = Ws[(kk + gc + 4) * 68 + nb];
        }
#pragma unroll
        for (int mf = 0; mf < 2; mf++)
#pragma unroll
            for (int nf = 0; nf < 2; nf++)
                mma_tf32(c[mf][nf], a[mf], bf[nf]);
    }

#pragma unroll
    for (int mf = 0; mf < 2; mf++) {
        int ra = wm0 + mf * 16 + gr, rb = ra + 8;
        int ta = ts[ra], tb = ts[rb];
#pragma unroll
        for (int nf = 0; nf < 2; nf++) {
            int col = wn0 + nf * 8 + 2 * gc;
            size_t oa = (size_t)ta * D_ + h * DH_ + col;
            size_t ob = (size_t)tb * D_ + h * DH_ + col;
            if (MODE == 0) {
                *(float2*)(g_vsel + oa) = make_float2(c[mf][nf][0], c[mf][nf][1]);
                *(float2*)(g_vsel + ob) = make_float2(c[mf][nf][2], c[mf][nf][3]);
            } else {
                float2 xa = *(const float2*)(xres + oa);
                float2 xb = *(const float2*)(xres + ob);
                *(float2*)(g_x1 + oa) = make_float2(xa.x + c[mf][nf][0], xa.y + c[mf][nf][1]);
                *(float2*)(g_x1 + ob) = make_float2(xb.x + c[mf][nf][2], xb.y + c[mf][nf][3]);
            }
        }
    }
}

// ---------------- attn pass1 body ----------------------------------------------
__device__ __forceinline__ void pass1_body(int s0, int h, int b, unsigned* dsp) {
    unsigned* uQ = dsp;
    unsigned* uK = dsp + 64 * 68;
    float* Ss = (float*)(dsp + 2 * 64 * 68);
    int tid = threadIdx.x, wid = tid >> 5, lane = tid & 31;
    int gr = lane >> 2, gc = lane & 3;
    const float* qb = g_q + (size_t)b * S_ * D_ + h * DH_;
    const float* kb = g_k + (size_t)b * S_ * D_ + h * DH_;
    {
        int r = tid >> 2, dg = (tid & 3) * 16;
        const float* src = qb + (size_t)(s0 + r) * D_ + dg;
#pragma unroll
        for (int i = 0; i < 4; i++) {
            float4 v = *(const float4*)(src + i * 4);
            uQ[r * 68 + dg + i * 4 + 0] = __float_as_uint(v.x);
            uQ[r * 68 + dg + i * 4 + 1] = __float_as_uint(v.y);
            uQ[r * 68 + dg + i * 4 + 2] = __float_as_uint(v.z);
            uQ[r * 68 + dg + i * 4 + 3] = __float_as_uint(v.w);
        }
    }
    const int wm0 = (wid & 1) * 32, wn0 = (wid >> 1) * 16;
    const int rr = tid >> 2, qq = tid & 3;
    float run_m = -INFINITY, run_l = 0.f;

    for (int t0 = 0; t0 <= s0; t0 += 64) {
        {
            int r = tid >> 2, dg = (tid & 3) * 16;
            const float* src = kb + (size_t)(t0 + r) * D_ + dg;
#pragma unroll
            for (int i = 0; i < 4; i++) {
                float4 v = *(const float4*)(src + i * 4);
                uK[(dg + i * 4 + 0) * 68 + r] = __float_as_uint(v.x);
                uK[(dg + i * 4 + 1) * 68 + r] = __float_as_uint(v.y);
                uK[(dg + i * 4 + 2) * 68 + r] = __float_as_uint(v.z);
                uK[(dg + i * 4 + 3) * 68 + r] = __float_as_uint(v.w);
            }
        }
        __syncthreads();
        float c[2][2][4];
#pragma unroll
        for (int mf = 0; mf < 2; mf++)
#pragma unroll
            for (int nf = 0; nf < 2; nf++)
#pragma unroll
                for (int q = 0; q < 4; q++) c[mf][nf][q] = 0.f;
#pragma unroll
        for (int kk = 0; kk < 64; kk += 8) {
            unsigned a[2][4], bf[2][2];
#pragma unroll
            for (int mf = 0; mf < 2; mf++) {
                int mb = wm0 + mf * 16;
                a[mf][0] = uQ[(mb + gr)     * 68 + kk + gc];
                a[mf][1] = uQ[(mb + gr + 8) * 68 + kk + gc];
                a[mf][2] = uQ[(mb + gr)     * 68 + kk + gc + 4];
                a[mf][3] = uQ[(mb + gr + 8) * 68 + kk + gc + 4];
            }
#pragma unroll
            for (int nf = 0; nf < 2; nf++) {
                int nb = wn0 + nf * 8 + gr;
                bf[nf][0] = uK[(kk + gc)     * 68 + nb];
                bf[nf][1] = uK[(kk + gc + 4) * 68 + nb];
            }
#pragma unroll
            for (int mf = 0; mf < 2; mf++)
#pragma unroll
                for (int nf = 0; nf < 2; nf++)
                    mma_tf32(c[mf][nf], a[mf], bf[nf]);
        }
#pragma unroll
        for (int mf = 0; mf < 2; mf++)
#pragma unroll
            for (int nf = 0; nf < 2; nf++) {
                int row = wm0 + mf * 16 + gr, col = wn0 + nf * 8 + 2 * gc;
                *(float2*)&Ss[row * 72 + col]       = make_float2(c[mf][nf][0], c[mf][nf][1]);
                *(float2*)&Ss[(row + 8) * 72 + col] = make_float2(c[mf][nf][2], c[mf][nf][3]);
            }
        __syncthreads();
        float v[16];
#pragma unroll
        for (int i = 0; i < 4; i++) {
            float4 t4 = *(const float4*)&Ss[rr * 72 + qq * 16 + i * 4];
            v[i * 4 + 0] = t4.x; v[i * 4 + 1] = t4.y; v[i * 4 + 2] = t4.z; v[i * 4 + 3] = t4.w;
        }
        int gs = s0 + rr;
        float mx = -INFINITY;
#pragma unroll
        for (int cI = 0; cI < 16; cI++) {
            int gt = t0 + qq * 16 + cI;
            if (gt <= gs) mx = fmaxf(mx, v[cI] * 0.125f);
        }
        mx = fmaxf(mx, __shfl_xor_sync(0xffffffffu, mx, 1));
        mx = fmaxf(mx, __shfl_xor_sync(0xffffffffu, mx, 2));
        float mn = fmaxf(run_m, mx);
        float alpha = __expf(run_m - mn);
        float sum = 0.f;
#pragma unroll
        for (int cI = 0; cI < 16; cI++) {
            int gt = t0 + qq * 16 + cI;
            if (gt <= gs) sum += __expf(v[cI] * 0.125f - mn);
        }
        sum += __shfl_xor_sync(0xffffffffu, sum, 1);
        sum += __shfl_xor_sync(0xffffffffu, sum, 2);
        run_l = run_l * alpha + sum;
        run_m = mn;
        __syncthreads();
    }
    if (qq == 0) {
        int o = (b * H_ + h) * S_ + s0 + rr;
        g_m[o] = run_m; g_l[o] = run_l;
    }
}

// ---------------- fused: attn pass1 + vsel gather GEMM -------------------------
// grid (16+48, 12, 2).  bx<16 -> pass1 (s0 reversed for tail balance).
// bx>=16 -> vsel tiles, grid-stride: id in [0,1152), he=id%96, tiles id/96, +12.
__global__ __launch_bounds__(256)
void pass1_vsel(const float* __restrict__ Wv) {
    extern __shared__ unsigned dsp[];
    int bx = blockIdx.x;
    if (bx < 16) {
        pass1_body((15 - bx) * 64, blockIdx.y, blockIdx.z, dsp);
    } else {
        int id = (bx - 16) + 48 * (blockIdx.y + 12 * blockIdx.z);
        int he = id % 96;
        int count = g_hcnt[he];
        for (int tile = id / 96; tile * 64 < count; tile += 12) {
            sel_body<0>(Wv, nullptr, he, tile, dsp);
            __syncthreads();
        }
    }
}

// ---------------- standalone osel gather GEMM ----------------------------------
__global__ __launch_bounds__(256)
void sel_gemm1(const float* __restrict__ Wo, const float* __restrict__ xres) {
    extern __shared__ unsigned dsp[];
    const int he = blockIdx.x;
    if (blockIdx.y * 64 >= g_hcnt[he]) return;
    sel_body<1>(Wo, xres, he, blockIdx.y, dsp);
}

// ---------------- attention pass 2 (tf32 MMA): out[t] = sum_s P[s,t] v[s] ------
__global__ __launch_bounds__(256)
void attn_pass2() {
    extern __shared__ unsigned dsp2[];
    unsigned* uK = dsp2;
    unsigned* uQ = dsp2 + 4352;
    unsigned* uV = dsp2 + 8704;
    unsigned* uP = dsp2 + 13056;
    float* srm  = (float*)(dsp2 + 17664);
    float* sinv = srm + 64;
    int t0 = blockIdx.x * 64, h = blockIdx.y, b = blockIdx.z;
    int tid = threadIdx.x, wid = tid >> 5, lane = tid & 31;
    int gr = lane >> 2, gc = lane & 3;
    const float* qb = g_q    + (size_t)b * S_ * D_ + h * DH_;
    const float* kb = g_k    + (size_t)b * S_ * D_ + h * DH_;
    const float* vb = g_vsel + (size_t)b * S_ * D_ + h * DH_;
    {
        int r = tid >> 2, dg = (tid & 3) * 16;
        const float* src = kb + (size_t)(t0 + r) * D_ + dg;
#pragma unroll
        for (int i = 0; i < 4; i++) {
            float4 v = *(const float4*)(src + i * 4);
            uK[(dg + i * 4 + 0) * 68 + r] = __float_as_uint(v.x);
            uK[(dg + i * 4 + 1) * 68 + r] = __float_as_uint(v.y);
            uK[(dg + i * 4 + 2) * 68 + r] = __float_as_uint(v.z);
            uK[(dg + i * 4 + 3) * 68 + r] = __float_as_uint(v.w);
        }
    }
    const int wm0 = (wid & 1) * 32, wn0 = (wid >> 1) * 16;
    float O[2][2][4];
#pragma unroll
    for (int mf = 0; mf < 2; mf++)
#pragma unroll
        for (int nf = 0; nf < 2; nf++)
#pragma unroll
            for (int q = 0; q < 4; q++) O[mf][nf][q] = 0.f;

    for (int st0 = t0; st0 < S_; st0 += 64) {
        {
            int r = tid >> 2, dg = (tid & 3) * 16;
            const float* qsrc = qb + (size_t)(st0 + r) * D_ + dg;
            const float* vsrc = vb + (size_t)(st0 + r) * D_ + dg;
#pragma unroll
            for (int i = 0; i < 4; i++) {
                float4 v = *(const float4*)(qsrc + i * 4);
                uQ[r * 68 + dg + i * 4 + 0] = __float_as_uint(v.x);
                uQ[r * 68 + dg + i * 4 + 1] = __float_as_uint(v.y);
                uQ[r * 68 + dg + i * 4 + 2] = __float_as_uint(v.z);
                uQ[r * 68 + dg + i * 4 + 3] = __float_as_uint(v.w);
                float4 w = *(const float4*)(vsrc + i * 4);
                uV[r * 68 + dg + i * 4 + 0] = __float_as_uint(w.x);
                uV[r * 68 + dg + i * 4 + 1] = __float_as_uint(w.y);
                uV[r * 68 + dg + i * 4 + 2] = __float_as_uint(w.z);
                uV[r * 68 + dg + i * 4 + 3] = __float_as_uint(w.w);
            }
        }
        if (tid < 64) {
            int o = (b * H_ + h) * S_ + st0 + tid;
            srm[tid] = g_m[o]; sinv[tid] = 1.f / g_l[o];
        }
        __syncthreads();
        float c[2][2][4];
#pragma unroll
        for (int mf = 0; mf < 2; mf++)
#pragma unroll
            for (int nf = 0; nf < 2; nf++)
#pragma unroll
                for (int q = 0; q < 4; q++) c[mf][nf][q] = 0.f;
#pragma unroll
        for (int kk = 0; kk < 64; kk += 8) {
            unsigned a[2][4], bf[2][2];
#pragma unroll
            for (int mf = 0; mf < 2; mf++) {
                int mb = wm0 + mf * 16;
                a[mf][0] = uQ[(mb + gr)     * 68 + kk + gc];
                a[mf][1] = uQ[(mb + gr + 8) * 68 + kk + gc];
                a[mf][2] = uQ[(mb + gr)     * 68 + kk + gc + 4];
                a[mf][3] = uQ[(mb + gr + 8) * 68 + kk + gc + 4];
            }
#pragma unroll
            for (int nf = 0; nf < 2; nf++) {
                int nb = wn0 + nf * 8 + gr;
                bf[nf][0] = uK[(kk + gc)     * 68 + nb];
                bf[nf][1] = uK[(kk + gc + 4) * 68 + nb];
            }
#pragma unroll
            for (int mf = 0; mf < 2; mf++)
#pragma unroll
                for (int nf = 0; nf < 2; nf++)
                    mma_tf32(c[mf][nf], a[mf], bf[nf]);
        }
#pragma unroll
        for (int mf = 0; mf < 2; mf++) {
            int sl_a = wm0 + mf * 16 + gr;
            int sl_b = sl_a + 8;
            int gs_a = st0 + sl_a, gs_b = st0 + sl_b;
            float ma = srm[sl_a], ia = sinv[sl_a];
            float mb2 = srm[sl_b], ib = sinv[sl_b];
#pragma unroll
            for (int nf = 0; nf < 2; nf++) {
                int tc = wn0 + nf * 8 + 2 * gc;
                int gt0 = t0 + tc, gt1 = gt0 + 1;
                float p;
                p = (gt0 <= gs_a) ? __expf(c[mf][nf][0] * 0.125f - ma) * ia : 0.f;
                uP[tc * 72 + sl_a] = to_tf32(p);
                p = (gt1 <= gs_a) ? __expf(c[mf][nf][1] * 0.125f - ma) * ia : 0.f;
                uP[(tc + 1) * 72 + sl_a] = to_tf32(p);
                p = (gt0 <= gs_b) ? __expf(c[mf][nf][2] * 0.125f - mb2) * ib : 0.f;
                uP[tc * 72 + sl_b] = to_tf32(p);
                p = (gt1 <= gs_b) ? __expf(c[mf][nf][3] * 0.125f - mb2) * ib : 0.f;
                uP[(tc + 1) * 72 + sl_b] = to_tf32(p);
            }
        }
        __syncthreads();
#pragma unroll
        for (int kk = 0; kk < 64; kk += 8) {
            unsigned a[2][4], bf[2][2];
#pragma unroll
            for (int mf = 0; mf < 2; mf++) {
                int mb = wm0 + mf * 16;
                a[mf][0] = uP[(mb + gr)     * 72 + kk + gc];
                a[mf][1] = uP[(mb + gr + 8) * 72 + kk + gc];
                a[mf][2] = uP[(mb + gr)     * 72 + kk + gc + 4];
                a[mf][3] = uP[(mb + gr + 8) * 72 + kk + gc + 4];
            }
#pragma unroll
            for (int nf = 0; nf < 2; nf++) {
                int nb = wn0 + nf * 8 + gr;
                bf[nf][0] = uV[(kk + gc)     * 68 + nb];
                bf[nf][1] = uV[(kk + gc + 4) * 68 + nb];
            }
#pragma unroll
            for (int mf = 0; mf < 2; mf++)
#pragma unroll
                for (int nf = 0; nf < 2; nf++)
                    mma_tf32(O[mf][nf], a[mf], bf[nf]);
        }
        __syncthreads();
    }
#pragma unroll
    for (int mf = 0; mf < 2; mf++) {
        int trow = t0 + wm0 + mf * 16 + gr;
#pragma unroll
        for (int nf = 0; nf < 2; nf++) {
            int fc = wn0 + nf * 8 + 2 * gc;
            *(float2*)(g_attn + (size_t)(b * S_ + trow) * D_ + h * DH_ + fc)
                = make_float2(O[mf][nf][0], O[mf][nf][1]);
            *(float2*)(g_attn + (size_t)(b * S_ + trow + 8) * D_ + h * DH_ + fc)
                = make_float2(O[mf][nf][2], O[mf][nf][3]);
        }
    }
}

// ---------------- capacity + deterministic slot assignment (smem staged) -------
__global__ void capacity_kernel() {
    __shared__ int sidx[NTOK * 2];
    int tid = threadIdx.x;
    for (int i = tid; i < NTOK * 2; i += 256) sidx[i] = g_tk_idx[i];
    __syncthreads();
    int w = tid >> 5, lane = tid & 31;
    if (w < E_) {
        int e = w, c = 0;
        for (int i0 = 0; i0 < NTOK * 2; i0 += 32) {
            int i = i0 + lane;
            int idx = sidx[i];
            bool match = (idx == e);
            unsigned msk = __ballot_sync(0xffffffffu, match);
            if (match) {
                int rank = c + __popc(msk & ((1u << lane) - 1u));
                if (rank < CAP_) {
                    g_slot_token[e * CAP_ + rank] = i >> 1;
                    g_token_slot[i] = e * CAP_ + rank;
                } else {
                    g_token_slot[i] = -1;
                }
            }
            c += __popc(msk);
        }
        if (lane == 0) g_ecount[e] = (c < CAP_) ? c : CAP_;
    }
    __syncthreads();
    for (int t = tid; t < NTOK; t += 256) {
        int s0 = g_token_slot[2 * t], s1 = g_token_slot[2 * t + 1];
        float p0 = (s0 >= 0) ? g_tk_prob[2 * t]     : 0.f;
        float p1 = (s1 >= 0) ? g_tk_prob[2 * t + 1] : 0.f;
        float inv = 1.f / (p0 + p1 + 1e-9f);
        if (s0 >= 0) g_slot_w[s0] = p0 * inv;
        if (s1 >= 0) g_slot_w[s1] = p1 * inv;
    }
}

// ---------------- combine + aux fused ------------------------------------------
__global__ void combine_kernel(float* __restrict__ out, int out_size) {
    int wid = threadIdx.x >> 5, lane = threadIdx.x & 31;
    int row = blockIdx.x * 8 + wid;
    int s0 = g_token_slot[2 * row], s1 = g_token_slot[2 * row + 1];
    const float4* xr = (const float4*)(g_x1 + (size_t)row * D_);
    const float4* f0 = (s0 >= 0) ? (const float4*)(g_sout + (size_t)s0 * D_) : nullptr;
    const float4* f1 = (s1 >= 0) ? (const float4*)(g_sout + (size_t)s1 * D_) : nullptr;
    float4* orow = (float4*)(out + (size_t)row * D_);
#pragma unroll
    for (int i = 0; i < 6; i++) {
        int c = lane + i * 32;
        float4 v = xr[c];
        if (f0) { float4 a = f0[c]; v.x += a.x; v.y += a.y; v.z += a.z; v.w += a.w; }
        if (f1) { float4 a = f1[c]; v.x += a.x; v.y += a.y; v.z += a.z; v.w += a.w; }
        orow[c] = v;
    }
    // block 0: aux losses appended after NOUT
    if (blockIdx.x == 0 && out_size > NOUT) {
        __shared__ float ic_sh[E_];
        __shared__ float sa;
        int tid = threadIdx.x, w = tid >> 5;
        if (w < E_) {
            int c = g_ecount[w];
            float s = 0.f;
            for (int r = lane; r < c; r += 32) s += g_slot_w[w * CAP_ + r];
#pragma unroll
            for (int o = 16; o > 0; o >>= 1) s += __shfl_down_sync(0xffffffffu, s, o);
            if (lane == 0) ic_sh[w] = s;
        }
        __syncthreads();
        if (tid == 0) {
            const float scale = 0.01f / 2048.f;
            float es = 0.f;
            for (int i = 0; i < H_ * E_; i++) es += g_hcnt[i] * scale;
            float a1 = 0.f;
            for (int i = 0; i < H_ * E_; i++) {
                float p = (g_hcnt[i] * scale) / (es + 1e-9f);
                a1 += p * p;
            }
            a1 *= (float)(E_ * H_);
            float tcs = 0.f, ics = 0.f;
            for (int e = 0; e < E_; e++) { tcs += (float)g_ecount[e]; ics += ic_sh[e]; }
            float a2 = 0.f;
            for (int e = 0; e < E_; e++) a2 += ((float)g_ecount[e] / tcs) * (ic_sh[e] / ics);
            a2 *= (float)E_;
            sa = a1 + a2;
        }
        __syncthreads();
        for (int i = NOUT + threadIdx.x; i < out_size; i += blockDim.x) out[i] = sa;
    }
}

// ---------------- launch -------------------------------------------------------
extern "C" void kernel_launch(void* const* d_in, const int* in_sizes, int n_in,
                              void* d_out, int out_size) {
    const float* x   = (const float*)d_in[0];
    // d_in[1] = mask (pure causal 0/-1e9, applied analytically)
    const float* Wq  = (const float*)d_in[2];
    const float* Wk  = (const float*)d_in[3];
    const float* Wv  = (const float*)d_in[4];
    const float* Wo  = (const float*)d_in[5];
    const float* Wr  = (const float*)d_in[6];
    const float* g1  = (const float*)d_in[7];
    const float* b1  = (const float*)d_in[8];
    const float* g2  = (const float*)d_in[9];
    const float* b2  = (const float*)d_in[10];
    const float* gff = (const float*)d_in[11];
    const float* W1  = (const float*)d_in[12];
    const float* W2  = (const float*)d_in[13];
    float* out = (float*)d_out;

    float *p_xln, *p_x1, *p_xln2;
    cudaGetSymbolAddress((void**)&p_xln,  g_xln);
    cudaGetSymbolAddress((void**)&p_x1,   g_x1);
    cudaGetSymbolAddress((void**)&p_xln2, g_xln2);

    const int pass1_smem = (2 * 64 * 68 + 64 * 72) * 4;           // 53248 B (covers sel body too)
    const int sel_smem   = (2 * 64 * 68 + 64) * 4;                // 35072 B
    const int pass2_smem = (3 * 64 * 68 + 64 * 72 + 128) * 4;
    cudaFuncSetAttribute(pass1_vsel, cudaFuncAttributeMaxDynamicSharedMemorySize, pass1_smem);
    cudaFuncSetAttribute(sel_gemm1,  cudaFuncAttributeMaxDynamicSharedMemorySize, sel_smem);
    cudaFuncSetAttribute(attn_pass2, cudaFuncAttributeMaxDynamicSharedMemorySize, pass2_smem);

    ln_kernel<<<NTOK / 8, 256>>>(x, g1, b1, p_xln, 1);
    gemm_tf32<0><<<dim3(26, NTOK / 128, 1), 256>>>(Wq, Wk, Wr);   // Q, K, router fused
    router_argmax<<<(NTOK * H_ + 255) / 256, 256>>>();
    pass1_vsel<<<dim3(64, H_, B_), 256, pass1_smem>>>(Wv);        // pass1 + vsel fused
    attn_pass2<<<dim3(S_ / 64, H_, B_), 256, pass2_smem>>>();
    sel_gemm1<<<dim3(H_ * E_, NTOK / 64), 256, sel_smem>>>(Wo, x);
    ln_gate_kernel<<<NTOK / 8, 256>>>(p_x1, g2, b2, gff, p_xln2);
    capacity_kernel<<<1, 256>>>();
    gemm_tf32<1><<<dim3(DFF_ / 64, (CAP_ + 127) / 128, E_), 256>>>(W1, nullptr, nullptr);
    gemm_tf32<2><<<dim3(D_ / 64, (CAP_ + 127) / 128, E_), 256>>>(W2, nullptr, nullptr);
    combine_kernel<<<NTOK / 8, 256>>>(out, out_size);
}

// round 17
// speedup vs baseline: 1.0193x; 1.0193x over previous
#include <cuda_runtime.h>
#include <math.h>

#define B_ 2
#define S_ 1024
#define D_ 768
#define H_ 12
#define E_ 8
#define DH_ 64
#define DFF_ 2048
#define NTOK (B_*S_)
#define CAP_ 320
#define NOUT (NTOK*D_)

// ---------------- scratch (device globals; no allocation allowed) -------------
__device__ float g_xln [NTOK*D_];
__device__ float g_q   [NTOK*D_];
__device__ float g_k   [NTOK*D_];
__device__ float g_vsel[NTOK*D_];
__device__ float g_attn[NTOK*D_];
__device__ float g_x1  [NTOK*D_];
__device__ float g_xln2[NTOK*D_];
__device__ float g_rlog[NTOK*(H_*E_)];
__device__ int   g_hcnt[H_*E_];
__device__ int   g_hlist[H_*E_*NTOK];
__device__ float g_m[B_*H_*S_];
__device__ float g_l[B_*H_*S_];
__device__ int   g_tk_idx[NTOK*2];
__device__ float g_tk_prob[NTOK*2];
__device__ int   g_token_slot[NTOK*2];
__device__ int   g_slot_token[E_*CAP_];
__device__ float g_slot_w[E_*CAP_];
__device__ int   g_ecount[E_];
__device__ float g_hbuf[E_*CAP_*DFF_];
__device__ float g_sout[E_*CAP_*D_];

// ---------------- tf32 tensor-core helpers -------------------------------------
__device__ __forceinline__ unsigned to_tf32(float f) {
    unsigned u; asm("cvt.rna.tf32.f32 %0,%1;" : "=r"(u) : "f"(f)); return u;
}
__device__ __forceinline__ void mma_tf32(float c[4], const unsigned a[4], const unsigned b[2]) {
    asm("mma.sync.aligned.m16n8k8.row.col.f32.tf32.tf32.f32 "
        "{%0,%1,%2,%3},{%4,%5,%6,%7},{%8,%9},{%0,%1,%2,%3};"
        : "+f"(c[0]), "+f"(c[1]), "+f"(c[2]), "+f"(c[3])
        : "r"(a[0]), "r"(a[1]), "r"(a[2]), "r"(a[3]), "r"(b[0]), "r"(b[1]));
}
__device__ __forceinline__ void cp16(void* smem, const void* g) {
    unsigned saddr = (unsigned)__cvta_generic_to_shared(smem);
    asm volatile("cp.async.cg.shared.global [%0], [%1], 16;" :: "r"(saddr), "l"(g));
}
#define CP_COMMIT() asm volatile("cp.async.commit_group;" ::: "memory")
#define CP_WAIT0()  asm volatile("cp.async.wait_group 0;" ::: "memory")

// ---------------- LayerNorm (warp per row, float4); optional counter clear -----
__global__ void ln_kernel(const float* __restrict__ x, const float* __restrict__ g,
                          const float* __restrict__ b, float* __restrict__ out,
                          int clear_hard) {
    if (clear_hard && blockIdx.x == 0 && threadIdx.x < H_ * E_) g_hcnt[threadIdx.x] = 0;
    int wid = threadIdx.x >> 5, lane = threadIdx.x & 31;
    int row = blockIdx.x * 8 + wid;
    const float4* xr = (const float4*)(x + (size_t)row * D_);
    float4 v[6];
    float s = 0.f, s2 = 0.f;
#pragma unroll
    for (int i = 0; i < 6; i++) {
        v[i] = xr[lane + i * 32];
        s  += v[i].x + v[i].y + v[i].z + v[i].w;
        s2 += v[i].x * v[i].x + v[i].y * v[i].y + v[i].z * v[i].z + v[i].w * v[i].w;
    }
#pragma unroll
    for (int o = 16; o > 0; o >>= 1) {
        s  += __shfl_xor_sync(0xffffffffu, s,  o);
        s2 += __shfl_xor_sync(0xffffffffu, s2, o);
    }
    float mean = s * (1.f / D_);
    float inv  = rsqrtf(s2 * (1.f / D_) - mean * mean + 1e-5f);
    float4* orow = (float4*)(out + (size_t)row * D_);
    const float4* g4 = (const float4*)g;
    const float4* b4 = (const float4*)b;
#pragma unroll
    for (int i = 0; i < 6; i++) {
        float4 gg = g4[lane + i * 32], bb = b4[lane + i * 32];
        float4 o;
        o.x = (v[i].x - mean) * inv * gg.x + bb.x;
        o.y = (v[i].y - mean) * inv * gg.y + bb.y;
        o.z = (v[i].z - mean) * inv * gg.z + bb.z;
        o.w = (v[i].w - mean) * inv * gg.w + bb.w;
        orow[lane + i * 32] = o;
    }
}

// ---------------- LN2 + FFN gate fused (warp per row, gff staged in smem) ------
__global__ void ln_gate_kernel(const float* __restrict__ x, const float* __restrict__ g,
                               const float* __restrict__ b, const float* __restrict__ gff,
                               float* __restrict__ out) {
    __shared__ float sgff[D_ * E_];   // 24 KB
    int tid = threadIdx.x;
    for (int i = tid; i < (D_ * E_) / 4; i += 256)
        *(float4*)&sgff[i * 4] = *(const float4*)(gff + i * 4);

    int wid = tid >> 5, lane = tid & 31;
    int row = blockIdx.x * 8 + wid;
    const float4* xr = (const float4*)(x + (size_t)row * D_);
    float4 v[6];
    float s = 0.f, s2 = 0.f;
#pragma unroll
    for (int i = 0; i < 6; i++) {
        v[i] = xr[lane + i * 32];
        s  += v[i].x + v[i].y + v[i].z + v[i].w;
        s2 += v[i].x * v[i].x + v[i].y * v[i].y + v[i].z * v[i].z + v[i].w * v[i].w;
    }
#pragma unroll
    for (int o = 16; o > 0; o >>= 1) {
        s  += __shfl_xor_sync(0xffffffffu, s,  o);
        s2 += __shfl_xor_sync(0xffffffffu, s2, o);
    }
    float mean = s * (1.f / D_);
    float inv  = rsqrtf(s2 * (1.f / D_) - mean * mean + 1e-5f);
    float4* orow = (float4*)(out + (size_t)row * D_);
    const float4* g4 = (const float4*)g;
    const float4* b4 = (const float4*)b;
    __syncthreads();
    float acc[8] = {};
#pragma unroll
    for (int i = 0; i < 6; i++) {
        int c = lane + i * 32;
        float4 gg = g4[c], bb = b4[c];
        float4 o;
        o.x = (v[i].x - mean) * inv * gg.x + bb.x;
        o.y = (v[i].y - mean) * inv * gg.y + bb.y;
        o.z = (v[i].z - mean) * inv * gg.z + bb.z;
        o.w = (v[i].w - mean) * inv * gg.w + bb.w;
        orow[c] = o;
        float ov[4] = { o.x, o.y, o.z, o.w };
#pragma unroll
        for (int j = 0; j < 4; j++) {
            float xv = ov[j];
            const float* gr = &sgff[(c * 4 + j) * E_];
            float4 gA = *(const float4*)gr;
            float4 gB = *(const float4*)(gr + 4);
            acc[0] += xv * gA.x; acc[1] += xv * gA.y; acc[2] += xv * gA.z; acc[3] += xv * gA.w;
            acc[4] += xv * gB.x; acc[5] += xv * gB.y; acc[6] += xv * gB.z; acc[7] += xv * gB.w;
        }
    }
#pragma unroll
    for (int off = 16; off > 0; off >>= 1)
#pragma unroll
        for (int i = 0; i < 8; i++)
            acc[i] += __shfl_down_sync(0xffffffffu, acc[i], off);
    if (lane == 0) {
        int i0 = 0; float v0 = acc[0];
#pragma unroll
        for (int e = 1; e < E_; e++) if (acc[e] > v0) { v0 = acc[e]; i0 = e; }
        int i1 = -1; float v1 = -3.4e38f;
#pragma unroll
        for (int e = 0; e < E_; e++) { if (e == i0) continue; if (acc[e] > v1) { v1 = acc[e]; i1 = e; } }
        float e1 = expf(v1 - v0);
        float z = 1.f + e1;
        g_tk_idx[row * 2] = i0; g_tk_idx[row * 2 + 1] = i1;
        g_tk_prob[row * 2] = 1.f / z; g_tk_prob[row * 2 + 1] = e1 / z;
    }
}

// ---------------- tf32 GEMM, 128x64x16 tiles, cp.async double buffered ---------
#define ASTRIDE 20
#define BSTRIDE 72
template<int MODE>
__global__ __launch_bounds__(256)
void gemm_tf32(const float* __restrict__ P0, const float* __restrict__ P1,
               const float* __restrict__ P2) {
    __shared__ __align__(16) unsigned As[2][128 * ASTRIDE];
    __shared__ __align__(16) unsigned Bs[2][16 * BSTRIDE];

    const int tid = threadIdx.x, wid = tid >> 5, lane = tid & 31;
    const int e  = blockIdx.z;
    const int m0 = blockIdx.y * 128;

    int N, K, count, n0;
    const float* Bm;
    float* C;
    const float* Abase;
    if (MODE == 0) {
        K = D_; count = NTOK; Abase = g_xln;
        int bx = blockIdx.x;
        if (bx < 12)      { Bm = P0; C = g_q;    N = D_; n0 = bx * 64; }
        else if (bx < 24) { Bm = P1; C = g_k;    N = D_; n0 = (bx - 12) * 64; }
        else              { Bm = P2; C = g_rlog; N = 96; n0 = (bx - 24) * 64; }
    } else if (MODE == 1) {
        N = DFF_; K = D_; count = g_ecount[e]; n0 = blockIdx.x * 64;
        if (count <= 0 || m0 >= count) return;
        Bm = P0 + (size_t)e * D_ * DFF_;
        C  = g_hbuf + (size_t)e * CAP_ * DFF_;
        Abase = g_xln2;
    } else {
        N = D_; K = DFF_; count = g_ecount[e]; n0 = blockIdx.x * 64;
        if (count <= 0 || m0 >= count) return;
        Bm = P0 + (size_t)e * DFF_ * D_;
        C  = g_sout + (size_t)e * CAP_ * D_;
        Abase = g_hbuf + (size_t)e * CAP_ * DFF_;
    }

    const int sm_r = tid >> 1;
    const int sm_k = (tid & 1) * 8;
    const int brow = tid >> 4;
    const int bcol = (tid & 15) * 4;

    const float* Aptr;
    {
        int r = m0 + sm_r;
        if (r >= count) r = count - 1;
        if (MODE == 1)
            Aptr = Abase + (size_t)g_slot_token[e * CAP_ + r] * D_ + sm_k;
        else
            Aptr = Abase + (size_t)r * K + sm_k;
    }
    int bc_eff = bcol;
    if (n0 + bcol + 4 > N) bc_eff = N - 4 - n0;
    const float* Bptr = Bm + (size_t)brow * N + n0 + bc_eff;

    const int wm0 = (wid & 3) * 32;
    const int wn0 = (wid >> 2) * 32;
    const int gr = lane >> 2, gc = lane & 3;

    float acc[2][4][4];
#pragma unroll
    for (int i = 0; i < 2; i++)
#pragma unroll
        for (int j = 0; j < 4; j++)
#pragma unroll
            for (int q = 0; q < 4; q++) acc[i][j][q] = 0.f;

    const int nk = K / 16;

    cp16(&As[0][sm_r * ASTRIDE + sm_k],     Aptr);
    cp16(&As[0][sm_r * ASTRIDE + sm_k + 4], Aptr + 4);
    cp16(&Bs[0][brow * BSTRIDE + bcol],     Bptr);
    CP_COMMIT();

    for (int kb = 0; kb < nk; kb++) {
        const int buf = kb & 1;
        CP_WAIT0();
        __syncthreads();
        if (kb + 1 < nk) {
            cp16(&As[buf ^ 1][sm_r * ASTRIDE + sm_k],     Aptr + (kb + 1) * 16);
            cp16(&As[buf ^ 1][sm_r * ASTRIDE + sm_k + 4], Aptr + (kb + 1) * 16 + 4);
            cp16(&Bs[buf ^ 1][brow * BSTRIDE + bcol],     Bptr + (size_t)(kb + 1) * 16 * N);
            CP_COMMIT();
        }
        const unsigned* Ab = As[buf];
        const unsigned* Bb = Bs[buf];
#pragma unroll
        for (int kk = 0; kk < 16; kk += 8) {
            unsigned a[2][4];
#pragma unroll
            for (int mf = 0; mf < 2; mf++) {
                int mb = wm0 + mf * 16;
                a[mf][0] = Ab[(mb + gr)     * ASTRIDE + kk + gc];
                a[mf][1] = Ab[(mb + gr + 8) * ASTRIDE + kk + gc];
                a[mf][2] = Ab[(mb + gr)     * ASTRIDE + kk + gc + 4];
                a[mf][3] = Ab[(mb + gr + 8) * ASTRIDE + kk + gc + 4];
            }
#pragma unroll
            for (int nf = 0; nf < 4; nf++) {
                int nb = wn0 + nf * 8 + gr;
                unsigned b[2];
                b[0] = Bb[(kk + gc)     * BSTRIDE + nb];
                b[1] = Bb[(kk + gc + 4) * BSTRIDE + nb];
                mma_tf32(acc[0][nf], a[0], b);
                mma_tf32(acc[1][nf], a[1], b);
            }
        }
    }

#pragma unroll
    for (int mf = 0; mf < 2; mf++) {
        int rbase = m0 + wm0 + mf * 16 + gr;
#pragma unroll
        for (int half = 0; half < 2; half++) {
            int r = rbase + half * 8;
            if (MODE != 0 && r >= count) continue;
            float w = 1.f;
            if (MODE == 2) w = g_slot_w[e * CAP_ + r];
#pragma unroll
            for (int nf = 0; nf < 4; nf++) {
                int cc = n0 + wn0 + nf * 8 + gc * 2;
                if (MODE == 0 && cc + 2 > N) continue;
                float v0 = acc[mf][nf][half * 2 + 0];
                float v1 = acc[mf][nf][half * 2 + 1];
                if (MODE == 1) { v0 = fmaxf(v0, 0.f); v1 = fmaxf(v1, 0.f); }
                else if (MODE == 2) { v0 *= w; v1 *= w; }
                *(float2*)(C + (size_t)r * N + cc) = make_float2(v0, v1);
            }
        }
    }
}

// ---------------- router argmax + per-(h,e) token list build -------------------
__global__ void router_argmax() {
    int idx = blockIdx.x * 256 + threadIdx.x;
    if (idx >= NTOK * H_) return;
    int row = idx / H_, h = idx - row * H_;
    const float* lg = g_rlog + (size_t)row * 96 + h * 8;
    float best = lg[0]; int bi = 0;
#pragma unroll
    for (int e = 1; e < E_; e++) { float v = lg[e]; if (v > best) { best = v; bi = e; } }
    int he = h * E_ + bi;
    int pos = atomicAdd(&g_hcnt[he], 1);
    g_hlist[(size_t)he * NTOK + pos] = row;
}

// ---------------- gathered expert GEMM for vsel/osel ---------------------------
template<int MODE>
__global__ __launch_bounds__(256)
void sel_gemm(const float* __restrict__ W, const float* __restrict__ xres) {
    __shared__ __align__(16) unsigned Xs[64 * 68];
    __shared__ __align__(16) unsigned Ws[64 * 68];
    __shared__ int ts[64];
    const int he = blockIdx.x;
    const int count = g_hcnt[he];
    const int tile = blockIdx.y;
    if (tile * 64 >= count) return;
    const int h = he >> 3;
    const int tid = threadIdx.x, wid = tid >> 5, lane = tid & 31;
    const int gr = lane >> 2, gc = lane & 3;

    if (tid < 64) {
        int idx = tile * 64 + tid;
        if (idx >= count) idx = count - 1;
        ts[tid] = g_hlist[(size_t)he * NTOK + idx];
    }
    __syncthreads();

    {
        int r = tid >> 2, cg = (tid & 3) * 16;
        const float* wsrc = W + (size_t)he * DH_ * DH_ + r * DH_ + cg;
        const float* xsrc = (MODE == 0 ? g_xln : g_attn) + (size_t)ts[r] * D_ + h * DH_ + cg;
#pragma unroll
        for (int i = 0; i < 4; i++) {
            float4 wv = *(const float4*)(wsrc + i * 4);
            Ws[r * 68 + cg + i * 4 + 0] = __float_as_uint(wv.x);
            Ws[r * 68 + cg + i * 4 + 1] = __float_as_uint(wv.y);
            Ws[r * 68 + cg + i * 4 + 2] = __float_as_uint(wv.z);
            Ws[r * 68 + cg + i * 4 + 3] = __float_as_uint(wv.w);
            float4 xv = *(const float4*)(xsrc + i * 4);
            Xs[r * 68 + cg + i * 4 + 0] = __float_as_uint(xv.x);
            Xs[r * 68 + cg + i * 4 + 1] = __float_as_uint(xv.y);
            Xs[r * 68 + cg + i * 4 + 2] = __float_as_uint(xv.z);
            Xs[r * 68 + cg + i * 4 + 3] = __float_as_uint(xv.w);
        }
    }
    __syncthreads();

    const int wm0 = (wid & 1) * 32, wn0 = (wid >> 1) * 16;
    float c[2][2][4];
#pragma unroll
    for (int mf = 0; mf < 2; mf++)
#pragma unroll
        for (int nf = 0; nf < 2; nf++)
#pragma unroll
            for (int q = 0; q < 4; q++) c[mf][nf][q] = 0.f;
#pragma unroll
    for (int kk = 0; kk < 64; kk += 8) {
        unsigned a[2][4], bf[2][2];
#pragma unroll
        for (int mf = 0; mf < 2; mf++) {
            int mb = wm0 + mf * 16;
            a[mf][0] = Xs[(mb + gr)     * 68 + kk + gc];
            a[mf][1] = Xs[(mb + gr + 8) * 68 + kk + gc];
            a[mf][2] = Xs[(mb + gr)     * 68 + kk + gc + 4];
            a[mf][3] = Xs[(mb + gr + 8) * 68 + kk + gc + 4];
        }
#pragma unroll
        for (int nf = 0; nf < 2; nf++) {
            int nb = wn0 + nf * 8 + gr;
            bf[nf][0] = Ws[(kk + gc)     * 68 + nb];
            bf[nf][1] = Ws[(kk + gc + 4) * 68 + nb];
        }
#pragma unroll
        for (int mf = 0; mf < 2; mf++)
#pragma unroll
            for (int nf = 0; nf < 2; nf++)
                mma_tf32(c[mf][nf], a[mf], bf[nf]);
    }

#pragma unroll
    for (int mf = 0; mf < 2; mf++) {
        int ra = wm0 + mf * 16 + gr, rb = ra + 8;
        int ta = ts[ra], tb = ts[rb];
#pragma unroll
        for (int nf = 0; nf < 2; nf++) {
            int col = wn0 + nf * 8 + 2 * gc;
            size_t oa = (size_t)ta * D_ + h * DH_ + col;
            size_t ob = (size_t)tb * D_ + h * DH_ + col;
            if (MODE == 0) {
                *(float2*)(g_vsel + oa) = make_float2(c[mf][nf][0], c[mf][nf][1]);
                *(float2*)(g_vsel + ob) = make_float2(c[mf][nf][2], c[mf][nf][3]);
            } else {
                float2 xa = *(const float2*)(xres + oa);
                float2 xb = *(const float2*)(xres + ob);
                *(float2*)(g_x1 + oa) = make_float2(xa.x + c[mf][nf][0], xa.y + c[mf][nf][1]);
                *(float2*)(g_x1 + ob) = make_float2(xb.x + c[mf][nf][2], xb.y + c[mf][nf][3]);
            }
        }
    }
}

// ---------------- attention pass 1 (tf32 MMA): row stats m_s, l_s --------------
__global__ __launch_bounds__(256)
void attn_pass1() {
    extern __shared__ unsigned dsp[];
    unsigned* uQ = dsp;
    unsigned* uK = dsp + 64 * 68;
    float* Ss = (float*)(dsp + 2 * 64 * 68);
    int s0 = blockIdx.x * 64, h = blockIdx.y, b = blockIdx.z;
    int tid = threadIdx.x, wid = tid >> 5, lane = tid & 31;
    int gr = lane >> 2, gc = lane & 3;
    const float* qb = g_q + (size_t)b * S_ * D_ + h * DH_;
    const float* kb = g_k + (size_t)b * S_ * D_ + h * DH_;
    {
        int r = tid >> 2, dg = (tid & 3) * 16;
        const float* src = qb + (size_t)(s0 + r) * D_ + dg;
#pragma unroll
        for (int i = 0; i < 4; i++) {
            float4 v = *(const float4*)(src + i * 4);
            uQ[r * 68 + dg + i * 4 + 0] = __float_as_uint(v.x);
            uQ[r * 68 + dg + i * 4 + 1] = __float_as_uint(v.y);
            uQ[r * 68 + dg + i * 4 + 2] = __float_as_uint(v.z);
            uQ[r * 68 + dg + i * 4 + 3] = __float_as_uint(v.w);
        }
    }
    const int wm0 = (wid & 1) * 32, wn0 = (wid >> 1) * 16;
    const int rr = tid >> 2, qq = tid & 3;
    float run_m = -INFINITY, run_l = 0.f;

    for (int t0 = 0; t0 <= s0; t0 += 64) {
        {
            int r = tid >> 2, dg = (tid & 3) * 16;
            const float* src = kb + (size_t)(t0 + r) * D_ + dg;
#pragma unroll
            for (int i = 0; i < 4; i++) {
                float4 v = *(const float4*)(src + i * 4);
                uK[(dg + i * 4 + 0) * 68 + r] = __float_as_uint(v.x);
                uK[(dg + i * 4 + 1) * 68 + r] = __float_as_uint(v.y);
                uK[(dg + i * 4 + 2) * 68 + r] = __float_as_uint(v.z);
                uK[(dg + i * 4 + 3) * 68 + r] = __float_as_uint(v.w);
            }
        }
        __syncthreads();
        float c[2][2][4];
#pragma unroll
        for (int mf = 0; mf < 2; mf++)
#pragma unroll
            for (int nf = 0; nf < 2; nf++)
#pragma unroll
                for (int q = 0; q < 4; q++) c[mf][nf][q] = 0.f;
#pragma unroll
        for (int kk = 0; kk < 64; kk += 8) {
            unsigned a[2][4], bf[2][2];
#pragma unroll
            for (int mf = 0; mf < 2; mf++) {
                int mb = wm0 + mf * 16;
                a[mf][0] = uQ[(mb + gr)     * 68 + kk + gc];
                a[mf][1] = uQ[(mb + gr + 8) * 68 + kk + gc];
                a[mf][2] = uQ[(mb + gr)     * 68 + kk + gc + 4];
                a[mf][3] = uQ[(mb + gr + 8) * 68 + kk + gc + 4];
            }
#pragma unroll
            for (int nf = 0; nf < 2; nf++) {
                int nb = wn0 + nf * 8 + gr;
                bf[nf][0] = uK[(kk + gc)     * 68 + nb];
                bf[nf][1] = uK[(kk + gc + 4) * 68 + nb];
            }
#pragma unroll
            for (int mf = 0; mf < 2; mf++)
#pragma unroll
                for (int nf = 0; nf < 2; nf++)
                    mma_tf32(c[mf][nf], a[mf], bf[nf]);
        }
#pragma unroll
        for (int mf = 0; mf < 2; mf++)
#pragma unroll
            for (int nf = 0; nf < 2; nf++) {
                int row = wm0 + mf * 16 + gr, col = wn0 + nf * 8 + 2 * gc;
                *(float2*)&Ss[row * 72 + col]       = make_float2(c[mf][nf][0], c[mf][nf][1]);
                *(float2*)&Ss[(row + 8) * 72 + col] = make_float2(c[mf][nf][2], c[mf][nf][3]);
            }
        __syncthreads();
        float v[16];
#pragma unroll
        for (int i = 0; i < 4; i++) {
            float4 t4 = *(const float4*)&Ss[rr * 72 + qq * 16 + i * 4];
            v[i * 4 + 0] = t4.x; v[i * 4 + 1] = t4.y; v[i * 4 + 2] = t4.z; v[i * 4 + 3] = t4.w;
        }
        int gs = s0 + rr;
        float mx = -INFINITY;
#pragma unroll
        for (int cI = 0; cI < 16; cI++) {
            int gt = t0 + qq * 16 + cI;
            if (gt <= gs) mx = fmaxf(mx, v[cI] * 0.125f);
        }
        mx = fmaxf(mx, __shfl_xor_sync(0xffffffffu, mx, 1));
        mx = fmaxf(mx, __shfl_xor_sync(0xffffffffu, mx, 2));
        float mn = fmaxf(run_m, mx);
        float alpha = __expf(run_m - mn);
        float sum = 0.f;
#pragma unroll
        for (int cI = 0; cI < 16; cI++) {
            int gt = t0 + qq * 16 + cI;
            if (gt <= gs) sum += __expf(v[cI] * 0.125f - mn);
        }
        sum += __shfl_xor_sync(0xffffffffu, sum, 1);
        sum += __shfl_xor_sync(0xffffffffu, sum, 2);
        run_l = run_l * alpha + sum;
        run_m = mn;
        __syncthreads();
    }
    if (qq == 0) {
        int o = (b * H_ + h) * S_ + s0 + rr;
        g_m[o] = run_m; g_l[o] = run_l;
    }
}

// ---------------- attention pass 2 (tf32 MMA): out[t] = sum_s P[s,t] v[s] ------
__global__ __launch_bounds__(256)
void attn_pass2() {
    extern __shared__ unsigned dsp2[];
    unsigned* uK = dsp2;
    unsigned* uQ = dsp2 + 4352;
    unsigned* uV = dsp2 + 8704;
    unsigned* uP = dsp2 + 13056;
    float* srm  = (float*)(dsp2 + 17664);
    float* sinv = srm + 64;
    int t0 = blockIdx.x * 64, h = blockIdx.y, b = blockIdx.z;
    int tid = threadIdx.x, wid = tid >> 5, lane = tid & 31;
    int gr = lane >> 2, gc = lane & 3;
    const float* qb = g_q    + (size_t)b * S_ * D_ + h * DH_;
    const float* kb = g_k    + (size_t)b * S_ * D_ + h * DH_;
    const float* vb = g_vsel + (size_t)b * S_ * D_ + h * DH_;
    {
        int r = tid >> 2, dg = (tid & 3) * 16;
        const float* src = kb + (size_t)(t0 + r) * D_ + dg;
#pragma unroll
        for (int i = 0; i < 4; i++) {
            float4 v = *(const float4*)(src + i * 4);
            uK[(dg + i * 4 + 0) * 68 + r] = __float_as_uint(v.x);
            uK[(dg + i * 4 + 1) * 68 + r] = __float_as_uint(v.y);
            uK[(dg + i * 4 + 2) * 68 + r] = __float_as_uint(v.z);
            uK[(dg + i * 4 + 3) * 68 + r] = __float_as_uint(v.w);
        }
    }
    const int wm0 = (wid & 1) * 32, wn0 = (wid >> 1) * 16;
    float O[2][2][4];
#pragma unroll
    for (int mf = 0; mf < 2; mf++)
#pragma unroll
        for (int nf = 0; nf < 2; nf++)
#pragma unroll
            for (int q = 0; q < 4; q++) O[mf][nf][q] = 0.f;

    for (int st0 = t0; st0 < S_; st0 += 64) {
        {
            int r = tid >> 2, dg = (tid & 3) * 16;
            const float* qsrc = qb + (size_t)(st0 + r) * D_ + dg;
            const float* vsrc = vb + (size_t)(st0 + r) * D_ + dg;
#pragma unroll
            for (int i = 0; i < 4; i++) {
                float4 v = *(const float4*)(qsrc + i * 4);
                uQ[r * 68 + dg + i * 4 + 0] = __float_as_uint(v.x);
                uQ[r * 68 + dg + i * 4 + 1] = __float_as_uint(v.y);
                uQ[r * 68 + dg + i * 4 + 2] = __float_as_uint(v.z);
                uQ[r * 68 + dg + i * 4 + 3] = __float_as_uint(v.w);
                float4 w = *(const float4*)(vsrc + i * 4);
                uV[r * 68 + dg + i * 4 + 0] = __float_as_uint(w.x);
                uV[r * 68 + dg + i * 4 + 1] = __float_as_uint(w.y);
                uV[r * 68 + dg + i * 4 + 2] = __float_as_uint(w.z);
                uV[r * 68 + dg + i * 4 + 3] = __float_as_uint(w.w);
            }
        }
        if (tid < 64) {
            int o = (b * H_ + h) * S_ + st0 + tid;
            srm[tid] = g_m[o]; sinv[tid] = 1.f / g_l[o];
        }
        __syncthreads();
        float c[2][2][4];
#pragma unroll
        for (int mf = 0; mf < 2; mf++)
#pragma unroll
            for (int nf = 0; nf < 2; nf++)
#pragma unroll
                for (int q = 0; q < 4; q++) c[mf][nf][q] = 0.f;
#pragma unroll
        for (int kk = 0; kk < 64; kk += 8) {
            unsigned a[2][4], bf[2][2];
#pragma unroll
            for (int mf = 0; mf < 2; mf++) {
                int mb = wm0 + mf * 16;
                a[mf][0] = uQ[(mb + gr)     * 68 + kk + gc];
                a[mf][1] = uQ[(mb + gr + 8) * 68 + kk + gc];
                a[mf][2] = uQ[(mb + gr)     * 68 + kk + gc + 4];
                a[mf][3] = uQ[(mb + gr + 8) * 68 + kk + gc + 4];
            }
#pragma unroll
            for (int nf = 0; nf < 2; nf++) {
                int nb = wn0 + nf * 8 + gr;
                bf[nf][0] = uK[(kk + gc)     * 68 + nb];
                bf[nf][1] = uK[(kk + gc + 4) * 68 + nb];
            }
#pragma unroll
            for (int mf = 0; mf < 2; mf++)
#pragma unroll
                for (int nf = 0; nf < 2; nf++)
                    mma_tf32(c[mf][nf], a[mf], bf[nf]);
        }
#pragma unroll
        for (int mf = 0; mf < 2; mf++) {
            int sl_a = wm0 + mf * 16 + gr;
            int sl_b = sl_a + 8;
            int gs_a = st0 + sl_a, gs_b = st0 + sl_b;
            float ma = srm[sl_a], ia = sinv[sl_a];
            float mb2 = srm[sl_b], ib = sinv[sl_b];
#pragma unroll
            for (int nf = 0; nf < 2; nf++) {
                int tc = wn0 + nf * 8 + 2 * gc;
                int gt0 = t0 + tc, gt1 = gt0 + 1;
                float p;
                p = (gt0 <= gs_a) ? __expf(c[mf][nf][0] * 0.125f - ma) * ia : 0.f;
                uP[tc * 72 + sl_a] = to_tf32(p);
                p = (gt1 <= gs_a) ? __expf(c[mf][nf][1] * 0.125f - ma) * ia : 0.f;
                uP[(tc + 1) * 72 + sl_a] = to_tf32(p);
                p = (gt0 <= gs_b) ? __expf(c[mf][nf][2] * 0.125f - mb2) * ib : 0.f;
                uP[tc * 72 + sl_b] = to_tf32(p);
                p = (gt1 <= gs_b) ? __expf(c[mf][nf][3] * 0.125f - mb2) * ib : 0.f;
                uP[(tc + 1) * 72 + sl_b] = to_tf32(p);
            }
        }
        __syncthreads();
#pragma unroll
        for (int kk = 0; kk < 64; kk += 8) {
            unsigned a[2][4], bf[2][2];
#pragma unroll
            for (int mf = 0; mf < 2; mf++) {
                int mb = wm0 + mf * 16;
                a[mf][0] = uP[(mb + gr)     * 72 + kk + gc];
                a[mf][1] = uP[(mb + gr + 8) * 72 + kk + gc];
                a[mf][2] = uP[(mb + gr)     * 72 + kk + gc + 4];
                a[mf][3] = uP[(mb + gr + 8) * 72 + kk + gc + 4];
            }
#pragma unroll
            for (int nf = 0; nf < 2; nf++) {
                int nb = wn0 + nf * 8 + gr;
                bf[nf][0] = uV[(kk + gc)     * 68 + nb];
                bf[nf][1] = uV[(kk + gc + 4) * 68 + nb];
            }
#pragma unroll
            for (int mf = 0; mf < 2; mf++)
#pragma unroll
                for (int nf = 0; nf < 2; nf++)
                    mma_tf32(O[mf][nf], a[mf], bf[nf]);
        }
        __syncthreads();
    }
#pragma unroll
    for (int mf = 0; mf < 2; mf++) {
        int trow = t0 + wm0 + mf * 16 + gr;
#pragma unroll
        for (int nf = 0; nf < 2; nf++) {
            int fc = wn0 + nf * 8 + 2 * gc;
            *(float2*)(g_attn + (size_t)(b * S_ + trow) * D_ + h * DH_ + fc)
                = make_float2(O[mf][nf][0], O[mf][nf][1]);
            *(float2*)(g_attn + (size_t)(b * S_ + trow + 8) * D_ + h * DH_ + fc)
                = make_float2(O[mf][nf][2], O[mf][nf][3]);
        }
    }
}

// ---------------- capacity + deterministic slot assignment (smem staged) -------
__global__ void capacity_kernel() {
    __shared__ int sidx[NTOK * 2];
    int tid = threadIdx.x;
    for (int i = tid; i < NTOK * 2; i += 256) sidx[i] = g_tk_idx[i];
    __syncthreads();
    int w = tid >> 5, lane = tid & 31;
    if (w < E_) {
        int e = w, c = 0;
        for (int i0 = 0; i0 < NTOK * 2; i0 += 32) {
            int i = i0 + lane;
            int idx = sidx[i];
            bool match = (idx == e);
            unsigned msk = __ballot_sync(0xffffffffu, match);
            if (match) {
                int rank = c + __popc(msk & ((1u << lane) - 1u));
                if (rank < CAP_) {
                    g_slot_token[e * CAP_ + rank] = i >> 1;
                    g_token_slot[i] = e * CAP_ + rank;
                } else {
                    g_token_slot[i] = -1;
                }
            }
            c += __popc(msk);
        }
        if (lane == 0) g_ecount[e] = (c < CAP_) ? c : CAP_;
    }
    __syncthreads();
    for (int t = tid; t < NTOK; t += 256) {
        int s0 = g_token_slot[2 * t], s1 = g_token_slot[2 * t + 1];
        float p0 = (s0 >= 0) ? g_tk_prob[2 * t]     : 0.f;
        float p1 = (s1 >= 0) ? g_tk_prob[2 * t + 1] : 0.f;
        float inv = 1.f / (p0 + p1 + 1e-9f);
        if (s0 >= 0) g_slot_w[s0] = p0 * inv;
        if (s1 >= 0) g_slot_w[s1] = p1 * inv;
    }
}

// ---------------- combine + aux fused ------------------------------------------
__global__ void combine_kernel(float* __restrict__ out, int out_size) {
    int wid = threadIdx.x >> 5, lane = threadIdx.x & 31;
    int row = blockIdx.x * 8 + wid;
    int s0 = g_token_slot[2 * row], s1 = g_token_slot[2 * row + 1];
    const float4* xr = (const float4*)(g_x1 + (size_t)row * D_);
    const float4* f0 = (s0 >= 0) ? (const float4*)(g_sout + (size_t)s0 * D_) : nullptr;
    const float4* f1 = (s1 >= 0) ? (const float4*)(g_sout + (size_t)s1 * D_) : nullptr;
    float4* orow = (float4*)(out + (size_t)row * D_);
#pragma unroll
    for (int i = 0; i < 6; i++) {
        int c = lane + i * 32;
        float4 v = xr[c];
        if (f0) { float4 a = f0[c]; v.x += a.x; v.y += a.y; v.z += a.z; v.w += a.w; }
        if (f1) { float4 a = f1[c]; v.x += a.x; v.y += a.y; v.z += a.z; v.w += a.w; }
        orow[c] = v;
    }
    if (blockIdx.x == 0 && out_size > NOUT) {
        __shared__ float ic_sh[E_];
        __shared__ float sa;
        int tid = threadIdx.x, w = tid >> 5;
        if (w < E_) {
            int c = g_ecount[w];
            float s = 0.f;
            for (int r = lane; r < c; r += 32) s += g_slot_w[w * CAP_ + r];
#pragma unroll
            for (int o = 16; o > 0; o >>= 1) s += __shfl_down_sync(0xffffffffu, s, o);
            if (lane == 0) ic_sh[w] = s;
        }
        __syncthreads();
        if (tid == 0) {
            const float scale = 0.01f / 2048.f;
            float es = 0.f;
            for (int i = 0; i < H_ * E_; i++) es += g_hcnt[i] * scale;
            float a1 = 0.f;
            for (int i = 0; i < H_ * E_; i++) {
                float p = (g_hcnt[i] * scale) / (es + 1e-9f);
                a1 += p * p;
            }
            a1 *= (float)(E_ * H_);
            float tcs = 0.f, ics = 0.f;
            for (int e = 0; e < E_; e++) { tcs += (float)g_ecount[e]; ics += ic_sh[e]; }
            float a2 = 0.f;
            for (int e = 0; e < E_; e++) a2 += ((float)g_ecount[e] / tcs) * (ic_sh[e] / ics);
            a2 *= (float)E_;
            sa = a1 + a2;
        }
        __syncthreads();
        for (int i = NOUT + threadIdx.x; i < out_size; i += blockDim.x) out[i] = sa;
    }
}

// ---------------- launch -------------------------------------------------------
extern "C" void kernel_launch(void* const* d_in, const int* in_sizes, int n_in,
                              void* d_out, int out_size) {
    const float* x   = (const float*)d_in[0];
    // d_in[1] = mask (pure causal 0/-1e9, applied analytically)
    const float* Wq  = (const float*)d_in[2];
    const float* Wk  = (const float*)d_in[3];
    const float* Wv  = (const float*)d_in[4];
    const float* Wo  = (const float*)d_in[5];
    const float* Wr  = (const float*)d_in[6];
    const float* g1  = (const float*)d_in[7];
    const float* b1  = (const float*)d_in[8];
    const float* g2  = (const float*)d_in[9];
    const float* b2  = (const float*)d_in[10];
    const float* gff = (const float*)d_in[11];
    const float* W1  = (const float*)d_in[12];
    const float* W2  = (const float*)d_in[13];
    float* out = (float*)d_out;

    float *p_xln, *p_x1, *p_xln2;
    cudaGetSymbolAddress((void**)&p_xln,  g_xln);
    cudaGetSymbolAddress((void**)&p_x1,   g_x1);
    cudaGetSymbolAddress((void**)&p_xln2, g_xln2);

    const int pass1_smem = (2 * 64 * 68 + 64 * 72) * 4;
    const int pass2_smem = (3 * 64 * 68 + 64 * 72 + 128) * 4;
    cudaFuncSetAttribute(attn_pass1, cudaFuncAttributeMaxDynamicSharedMemorySize, pass1_smem);
    cudaFuncSetAttribute(attn_pass2, cudaFuncAttributeMaxDynamicSharedMemorySize, pass2_smem);

    ln_kernel<<<NTOK / 8, 256>>>(x, g1, b1, p_xln, 1);
    gemm_tf32<0><<<dim3(26, NTOK / 128, 1), 256>>>(Wq, Wk, Wr);   // Q, K, router fused
    router_argmax<<<(NTOK * H_ + 255) / 256, 256>>>();
    sel_gemm<0><<<dim3(H_ * E_, NTOK / 64), 256>>>(Wv, nullptr);
    attn_pass1<<<dim3(S_ / 64, H_, B_), 256, pass1_smem>>>();
    attn_pass2<<<dim3(S_ / 64, H_, B_), 256, pass2_smem>>>();
    sel_gemm<1><<<dim3(H_ * E_, NTOK / 64), 256>>>(Wo, x);
    ln_gate_kernel<<<NTOK / 8, 256>>>(p_x1, g2, b2, gff, p_xln2);
    capacity_kernel<<<1, 256>>>();
    gemm_tf32<1><<<dim3(DFF_ / 64, (CAP_ + 127) / 128, E_), 256>>>(W1, nullptr, nullptr);
    gemm_tf32<2><<<dim3(D_ / 64, (CAP_ + 127) / 128, E_), 256>>>(W2, nullptr, nullptr);
    combine_kernel<<<NTOK / 8, 256>>>(out, out_size);
}